// round 7
// baseline (speedup 1.0000x reference)
#include <cuda_runtime.h>
#include <cstdint>

// Problem constants (fixed by the dataset)
#define BATCH 2
#define CH    3
#define IMH   256
#define IMW   320
#define NDEPTH 64
#define HW    (IMH * IMW)          // 81920
#define DHW   (NDEPTH * HW)        // 5242880
#define CHW   (CH * HW)

// Precomputed projection: proj = src_proj @ inv(gt_proj); rows 0..2.
// [batch][src: 0=left, 1=right]
__device__ float g_rot[BATCH][2][9];
__device__ float g_trans[BATCH][2][3];

// ---------------------------------------------------------------------------
// Setup: invert gt_proj (4x4, double Gauss-Jordan w/ pivoting), compute
// src_proj @ inv(gt_proj), store rot (3x3) + trans (3) per batch/src.
// ---------------------------------------------------------------------------
__device__ void invert4(const float* mf, double* inv) {
    double a[4][8];
    for (int i = 0; i < 4; i++)
        for (int j = 0; j < 4; j++) {
            a[i][j]     = (double)mf[i * 4 + j];
            a[i][4 + j] = (i == j) ? 1.0 : 0.0;
        }
    for (int col = 0; col < 4; col++) {
        int piv = col;
        double best = fabs(a[col][col]);
        for (int r = col + 1; r < 4; r++) {
            double v = fabs(a[r][col]);
            if (v > best) { best = v; piv = r; }
        }
        if (piv != col)
            for (int j = 0; j < 8; j++) {
                double t = a[col][j]; a[col][j] = a[piv][j]; a[piv][j] = t;
            }
        double p = a[col][col];
        for (int j = 0; j < 8; j++) a[col][j] /= p;
        for (int r = 0; r < 4; r++) {
            if (r == col) continue;
            double f = a[r][col];
            for (int j = 0; j < 8; j++) a[r][j] -= f * a[col][j];
        }
    }
    for (int i = 0; i < 4; i++)
        for (int j = 0; j < 4; j++) inv[i * 4 + j] = a[i][4 + j];
}

__global__ void setup_mats_kernel(const float* __restrict__ left_proj,
                                  const float* __restrict__ right_proj,
                                  const float* __restrict__ gt_proj) {
    if (threadIdx.x != 0 || blockIdx.x != 0) return;
    for (int b = 0; b < BATCH; b++) {
        double inv[16];
        invert4(gt_proj + b * 16, inv);
        const float* srcs[2] = { left_proj + b * 16, right_proj + b * 16 };
        for (int s = 0; s < 2; s++) {
            for (int i = 0; i < 3; i++) {
                for (int j = 0; j < 4; j++) {
                    double acc = 0.0;
                    for (int k = 0; k < 4; k++)
                        acc += (double)srcs[s][i * 4 + k] * inv[k * 4 + j];
                    if (j < 3) g_rot[b][s][i * 3 + j] = (float)acc;
                    else       g_trans[b][s][i]       = (float)acc;
                }
            }
        }
    }
}

// ---------------------------------------------------------------------------
// JAX threefry2x32 (20 rounds), PARTITIONABLE counter-mode (default in
// modern JAX): for output element i, counter = uint64(i) -> (hi=0, lo=i),
// (o0, o1) = threefry2x32(key, (0, i)), and 32-bit bits = o0 ^ o1.
// key = (0, 1) for jax.random.key(1).
// ---------------------------------------------------------------------------
__device__ __forceinline__ uint32_t rotl32(uint32_t v, int d) {
    return (v << d) | (v >> (32 - d));
}

__device__ __forceinline__ uint32_t threefry_xor_bits(uint32_t c1) {
    const uint32_t k0 = 0u, k1 = 1u;
    const uint32_t ks2 = k0 ^ k1 ^ 0x1BD11BDAu;   // = 0x1BD11BDB
    uint32_t x0 = 0u + k0;      // c0 = 0
    uint32_t x1 = c1 + k1;
#define TF_RND(r) { x0 += x1; x1 = rotl32(x1, (r)); x1 ^= x0; }
    TF_RND(13) TF_RND(15) TF_RND(26) TF_RND(6)
    x0 += k1;  x1 += ks2 + 1u;
    TF_RND(17) TF_RND(29) TF_RND(16) TF_RND(24)
    x0 += ks2; x1 += k0 + 2u;
    TF_RND(13) TF_RND(15) TF_RND(26) TF_RND(6)
    x0 += k0;  x1 += k1 + 3u;
    TF_RND(17) TF_RND(29) TF_RND(16) TF_RND(24)
    x0 += k1;  x1 += ks2 + 4u;
    TF_RND(13) TF_RND(15) TF_RND(26) TF_RND(6)
    x0 += ks2; x1 += k0 + 5u;
#undef TF_RND
    return x0 ^ x1;
}

// bits -> uniform [0,1): bitcast(bits>>9 | 0x3f800000) - 1
__device__ __forceinline__ float bits_to_uniform(uint32_t bits) {
    return __uint_as_float((bits >> 9) | 0x3f800000u) - 1.0f;
}

// ---------------------------------------------------------------------------
// Bilinear sample with zeros padding (align_corners=True pixel coords),
// 3 channels at once. Matches reference corner order and weighting exactly
// (weight * valid, clipped gather indices).
// ---------------------------------------------------------------------------
__device__ __forceinline__ void bilin3(const float* __restrict__ img,
                                       float px, float py, float v[3]) {
    float x0f = floorf(px), y0f = floorf(py);
    float wx1 = px - x0f,   wy1 = py - y0f;
    float wx0 = 1.0f - wx1, wy0 = 1.0f - wy1;
    v[0] = 0.0f; v[1] = 0.0f; v[2] = 0.0f;
#pragma unroll
    for (int cy = 0; cy < 2; cy++) {
#pragma unroll
        for (int cx = 0; cx < 2; cx++) {
            float xc = x0f + (float)cx;
            float yc = y0f + (float)cy;
            bool valid = (xc >= 0.0f) && (xc <= (float)(IMW - 1)) &&
                         (yc >= 0.0f) && (yc <= (float)(IMH - 1));
            int xi = min(max((int)xc, 0), IMW - 1);
            int yi = min(max((int)yc, 0), IMH - 1);
            float wgt = (cx ? wx1 : wx0) * (cy ? wy1 : wy0);
            wgt = valid ? wgt : 0.0f;
            int off = yi * IMW + xi;
            v[0] = fmaf(wgt, __ldg(img + off),          v[0]);
            v[1] = fmaf(wgt, __ldg(img + HW + off),     v[1]);
            v[2] = fmaf(wgt, __ldg(img + 2 * HW + off), v[2]);
        }
    }
}

// ---------------------------------------------------------------------------
// Main fused kernel: one thread per (d, h, w), handles BOTH batches.
// Flat noise index for (b,d,h,w) = b*DHW + idx; counter-mode threefry, so
// two independent evaluations (good ILP, chains interleave).
// ---------------------------------------------------------------------------
__global__ void __launch_bounds__(256)
volume_kernel(const float* __restrict__ left_img,
              const float* __restrict__ right_img,
              float* __restrict__ out) {
    int idx = blockIdx.x * blockDim.x + threadIdx.x;
    if (idx >= DHW) return;

    int d   = idx / HW;
    int rem = idx - d * HW;
    int h   = rem / IMW;
    int w   = rem - h * IMW;

    float noise[2];
    noise[0] = bits_to_uniform(threefry_xor_bits((uint32_t)idx));
    noise[1] = bits_to_uniform(threefry_xor_bits((uint32_t)(idx + DHW)));

    const float INVMAX = (float)(1.0 / 40.0);
    const float DIFFI  = (float)(1.0 / 10.0 - 1.0 / 40.0);
    float fd = (float)d;
    float wf = (float)w;
    float hf = (float)h;

#pragma unroll
    for (int b = 0; b < BATCH; b++) {
        float s = noise[b] + fd;
        float den = fmaf(s * (1.0f / NDEPTH), DIFFI, INVMAX);
        float depth = __fdividef(1.0f, den);

        float v[2][3];   // [src][channel]
        const float* imgs[2] = { left_img + b * CHW, right_img + b * CHW };
#pragma unroll
        for (int src = 0; src < 2; src++) {
            const float* R = g_rot[b][src];
            const float* T = g_trans[b][src];
            float rx = fmaf(R[0], wf, fmaf(R[1], hf, R[2]));
            float ry = fmaf(R[3], wf, fmaf(R[4], hf, R[5]));
            float rz = fmaf(R[6], wf, fmaf(R[7], hf, R[8]));

            float pz = fmaf(rz, depth, T[2]);
            bool neg = pz <= 0.001f;
            float z  = neg ? 1.0f : pz;
            float pxn = neg ? (float)IMW : fmaf(rx, depth, T[0]);
            float pyn = neg ? (float)IMH : fmaf(ry, depth, T[1]);
            float px = __fdividef(pxn, z);
            float py = __fdividef(pyn, z);

            bilin3(imgs[src], px, py, v[src]);
        }

        float r = fabsf(v[1][0] - v[0][0]) +
                  fabsf(v[1][1] - v[0][1]) +
                  fabsf(v[1][2] - v[0][2]);
        out[b * DHW + idx] = r;
    }
}

extern "C" void kernel_launch(void* const* d_in, const int* in_sizes, int n_in,
                              void* d_out, int out_size) {
    const float* left_img   = (const float*)d_in[0];
    const float* right_img  = (const float*)d_in[1];
    const float* left_proj  = (const float*)d_in[2];
    const float* right_proj = (const float*)d_in[3];
    const float* gt_proj    = (const float*)d_in[4];
    float* out = (float*)d_out;

    setup_mats_kernel<<<1, 32>>>(left_proj, right_proj, gt_proj);

    const int threads = 256;
    const int blocks = (DHW + threads - 1) / threads;  // 20480
    volume_kernel<<<blocks, threads>>>(left_img, right_img, out);
}

// round 10
// speedup vs baseline: 1.4150x; 1.4150x over previous
#include <cuda_runtime.h>
#include <cstdint>

// Problem constants (fixed by the dataset)
#define BATCH 2
#define CH    3
#define IMH   256
#define IMW   320
#define NDEPTH 64
#define HW    (IMH * IMW)          // 81920
#define DHW   (NDEPTH * HW)        // 5242880
#define CHW   (CH * HW)

#define DCHUNK 8                   // depths per thread
#define NCHUNK (NDEPTH / DCHUNK)   // 8
#define BLKS_PER_CHUNK (HW / 256)  // 320

// Precomputed projection: proj = src_proj @ inv(gt_proj); rows 0..2.
// [batch][src: 0=left, 1=right]
__device__ float g_rot[BATCH][2][9];
__device__ float g_trans[BATCH][2][3];

// ---------------------------------------------------------------------------
// Setup: 4x4 inverse via cofactor/adjugate (ONE double division instead of
// 32 serial DDIVs of Gauss-Jordan — this kernel was ~40us of the runtime).
// One thread per batch.
// ---------------------------------------------------------------------------
__device__ void invert4_adj(const float* mf, double* inv) {
    double m[16];
    for (int i = 0; i < 16; i++) m[i] = (double)mf[i];

    double a0 = m[0]*m[5]  - m[1]*m[4];
    double a1 = m[0]*m[6]  - m[2]*m[4];
    double a2 = m[0]*m[7]  - m[3]*m[4];
    double a3 = m[1]*m[6]  - m[2]*m[5];
    double a4 = m[1]*m[7]  - m[3]*m[5];
    double a5 = m[2]*m[7]  - m[3]*m[6];
    double b0 = m[8]*m[13] - m[9]*m[12];
    double b1 = m[8]*m[14] - m[10]*m[12];
    double b2 = m[8]*m[15] - m[11]*m[12];
    double b3 = m[9]*m[14] - m[10]*m[13];
    double b4 = m[9]*m[15] - m[11]*m[13];
    double b5 = m[10]*m[15]- m[11]*m[14];

    double det = a0*b5 - a1*b4 + a2*b3 + a3*b2 - a4*b1 + a5*b0;
    double id = 1.0 / det;

    inv[0]  = ( m[5]*b5  - m[6]*b4  + m[7]*b3) * id;
    inv[1]  = (-m[1]*b5  + m[2]*b4  - m[3]*b3) * id;
    inv[2]  = ( m[13]*a5 - m[14]*a4 + m[15]*a3) * id;
    inv[3]  = (-m[9]*a5  + m[10]*a4 - m[11]*a3) * id;
    inv[4]  = (-m[4]*b5  + m[6]*b2  - m[7]*b1) * id;
    inv[5]  = ( m[0]*b5  - m[2]*b2  + m[3]*b1) * id;
    inv[6]  = (-m[12]*a5 + m[14]*a2 - m[15]*a1) * id;
    inv[7]  = ( m[8]*a5  - m[10]*a2 + m[11]*a1) * id;
    inv[8]  = ( m[4]*b4  - m[5]*b2  + m[7]*b0) * id;
    inv[9]  = (-m[0]*b4  + m[1]*b2  - m[3]*b0) * id;
    inv[10] = ( m[12]*a4 - m[13]*a2 + m[15]*a0) * id;
    inv[11] = (-m[8]*a4  + m[9]*a2  - m[11]*a0) * id;
    inv[12] = (-m[4]*b3  + m[5]*b1  - m[6]*b0) * id;
    inv[13] = ( m[0]*b3  - m[1]*b1  + m[2]*b0) * id;
    inv[14] = (-m[12]*a3 + m[13]*a1 - m[14]*a0) * id;
    inv[15] = ( m[8]*a3  - m[9]*a1  + m[10]*a0) * id;
}

__global__ void setup_mats_kernel(const float* __restrict__ left_proj,
                                  const float* __restrict__ right_proj,
                                  const float* __restrict__ gt_proj) {
    int b = threadIdx.x;
    if (b >= BATCH || blockIdx.x != 0) return;
    double inv[16];
    invert4_adj(gt_proj + b * 16, inv);
    const float* srcs[2] = { left_proj + b * 16, right_proj + b * 16 };
    for (int s = 0; s < 2; s++) {
        for (int i = 0; i < 3; i++) {
            for (int j = 0; j < 4; j++) {
                double acc = 0.0;
                for (int k = 0; k < 4; k++)
                    acc += (double)srcs[s][i * 4 + k] * inv[k * 4 + j];
                if (j < 3) g_rot[b][s][i * 3 + j] = (float)acc;
                else       g_trans[b][s][i]       = (float)acc;
            }
        }
    }
}

// ---------------------------------------------------------------------------
// JAX threefry2x32 (20 rounds), partitionable counter-mode:
// counter = (0, i); 32-bit output bits = x0 ^ x1; key = (0,1).
// ---------------------------------------------------------------------------
__device__ __forceinline__ uint32_t rotl32(uint32_t v, int d) {
    return __funnelshift_l(v, v, d);
}

__device__ __forceinline__ uint32_t threefry_xor_bits(uint32_t c1) {
    const uint32_t k0 = 0u, k1 = 1u;
    const uint32_t ks2 = k0 ^ k1 ^ 0x1BD11BDAu;
    uint32_t x0 = 0u + k0;
    uint32_t x1 = c1 + k1;
#define TF_RND(r) { x0 += x1; x1 = rotl32(x1, (r)); x1 ^= x0; }
    TF_RND(13) TF_RND(15) TF_RND(26) TF_RND(6)
    x0 += k1;  x1 += ks2 + 1u;
    TF_RND(17) TF_RND(29) TF_RND(16) TF_RND(24)
    x0 += ks2; x1 += k0 + 2u;
    TF_RND(13) TF_RND(15) TF_RND(26) TF_RND(6)
    x0 += k0;  x1 += k1 + 3u;
    TF_RND(17) TF_RND(29) TF_RND(16) TF_RND(24)
    x0 += k1;  x1 += ks2 + 4u;
    TF_RND(13) TF_RND(15) TF_RND(26) TF_RND(6)
    x0 += ks2; x1 += k0 + 5u;
#undef TF_RND
    return x0 ^ x1;
}

__device__ __forceinline__ float bits_to_uniform(uint32_t bits) {
    return __uint_as_float((bits >> 9) | 0x3f800000u) - 1.0f;
}

// ---------------------------------------------------------------------------
// Bilinear, zeros padding — corner-hoisted form. Validity factorizes:
// weight(corner) = (wx*vx) * (wy*vy), so compute per-axis masked weights
// and the 4 clamped offsets ONCE, then 12 LDG + 12 FFMA.
// Corner accumulation order matches reference: (x0,y0),(x1,y0),(x0,y1),(x1,y1).
// ---------------------------------------------------------------------------
__device__ __forceinline__ void bilin3(const float* __restrict__ img,
                                       float px, float py, float v[3]) {
    float x0f = floorf(px), y0f = floorf(py);
    float wx1 = px - x0f,   wy1 = py - y0f;
    float wx0 = 1.0f - wx1, wy0 = 1.0f - wy1;
    float x1f = x0f + 1.0f, y1f = y0f + 1.0f;

    float ax0 = (x0f >= 0.0f && x0f <= (float)(IMW - 1)) ? wx0 : 0.0f;
    float ax1 = (x1f >= 0.0f && x1f <= (float)(IMW - 1)) ? wx1 : 0.0f;
    float ay0 = (y0f >= 0.0f && y0f <= (float)(IMH - 1)) ? wy0 : 0.0f;
    float ay1 = (y1f >= 0.0f && y1f <= (float)(IMH - 1)) ? wy1 : 0.0f;

    int xi0 = min(max((int)x0f, 0), IMW - 1);
    int xi1 = min(max((int)x1f, 0), IMW - 1);
    int yi0 = min(max((int)y0f, 0), IMH - 1);
    int yi1 = min(max((int)y1f, 0), IMH - 1);

    int r0 = yi0 * IMW, r1 = yi1 * IMW;
    int o00 = r0 + xi0, o10 = r0 + xi1, o01 = r1 + xi0, o11 = r1 + xi1;
    float w00 = ax0 * ay0, w10 = ax1 * ay0, w01 = ax0 * ay1, w11 = ax1 * ay1;

#pragma unroll
    for (int c = 0; c < CH; c++) {
        const float* p = img + c * HW;
        float acc;
        acc = w00 * __ldg(p + o00);
        acc = fmaf(w10, __ldg(p + o10), acc);
        acc = fmaf(w01, __ldg(p + o01), acc);
        acc = fmaf(w11, __ldg(p + o11), acc);
        v[c] = acc;
    }
}

// ---------------------------------------------------------------------------
// Main fused kernel: one thread per (h, w, depth-chunk of 8).
// Per-thread hoisted out of the d-loop: (h,w) decode, the 48 matrix LDGs,
// and the 24 ray FMAs (rays depend only on (h,w,b,src), not depth).
// ---------------------------------------------------------------------------
__global__ void __launch_bounds__(256)
volume_kernel(const float* __restrict__ left_img,
              const float* __restrict__ right_img,
              float* __restrict__ out) {
    int chunk = blockIdx.x / BLKS_PER_CHUNK;
    int hw    = (blockIdx.x % BLKS_PER_CHUNK) * 256 + threadIdx.x;

    int h = hw / IMW;
    int w = hw - h * IMW;
    float wf = (float)w, hf = (float)h;

    // Hoist ray directions + translations for all 4 (b,src) combos.
    float rx[2][2], ry[2][2], rz[2][2], tx[2][2], ty[2][2], tz[2][2];
#pragma unroll
    for (int b = 0; b < BATCH; b++)
#pragma unroll
        for (int s = 0; s < 2; s++) {
            const float* R = g_rot[b][s];
            const float* T = g_trans[b][s];
            rx[b][s] = fmaf(R[0], wf, fmaf(R[1], hf, R[2]));
            ry[b][s] = fmaf(R[3], wf, fmaf(R[4], hf, R[5]));
            rz[b][s] = fmaf(R[6], wf, fmaf(R[7], hf, R[8]));
            tx[b][s] = T[0]; ty[b][s] = T[1]; tz[b][s] = T[2];
        }

    const float* imgs[2][2] = {
        { left_img,       right_img       },
        { left_img + CHW, right_img + CHW }
    };

    const float INVMAX = (float)(1.0 / 40.0);
    const float DIFFI  = (float)(1.0 / 10.0 - 1.0 / 40.0);

    int d0  = chunk * DCHUNK;
    int idx = d0 * HW + hw;

#pragma unroll 2
    for (int i = 0; i < DCHUNK; i++, idx += HW) {
        float fd = (float)(d0 + i);

        float noise[2];
        noise[0] = bits_to_uniform(threefry_xor_bits((uint32_t)idx));
        noise[1] = bits_to_uniform(threefry_xor_bits((uint32_t)(idx + DHW)));

#pragma unroll
        for (int b = 0; b < BATCH; b++) {
            float s = noise[b] + fd;
            float den = fmaf(s * (1.0f / NDEPTH), DIFFI, INVMAX);
            float depth = __fdividef(1.0f, den);

            float v[2][3];
#pragma unroll
            for (int src = 0; src < 2; src++) {
                float pz = fmaf(rz[b][src], depth, tz[b][src]);
                bool neg = pz <= 0.001f;
                float z   = neg ? 1.0f : pz;
                float pxn = neg ? (float)IMW : fmaf(rx[b][src], depth, tx[b][src]);
                float pyn = neg ? (float)IMH : fmaf(ry[b][src], depth, ty[b][src]);
                float invz = __fdividef(1.0f, z);
                float px = pxn * invz;
                float py = pyn * invz;
                bilin3(imgs[b][src], px, py, v[src]);
            }

            float r = fabsf(v[1][0] - v[0][0]) +
                      fabsf(v[1][1] - v[0][1]) +
                      fabsf(v[1][2] - v[0][2]);
            out[b * DHW + idx] = r;
        }
    }
}

extern "C" void kernel_launch(void* const* d_in, const int* in_sizes, int n_in,
                              void* d_out, int out_size) {
    const float* left_img   = (const float*)d_in[0];
    const float* right_img  = (const float*)d_in[1];
    const float* left_proj  = (const float*)d_in[2];
    const float* right_proj = (const float*)d_in[3];
    const float* gt_proj    = (const float*)d_in[4];
    float* out = (float*)d_out;

    setup_mats_kernel<<<1, 32>>>(left_proj, right_proj, gt_proj);

    const int blocks = NCHUNK * BLKS_PER_CHUNK;  // 2560
    volume_kernel<<<blocks, 256>>>(left_img, right_img, out);
}